// round 5
// baseline (speedup 1.0000x reference)
#include <cuda_runtime.h>
#include <cuda_fp16.h>
#include <cstdint>

#define NB 64
#define NS 2048
#define ND 512
#define NU 512

// -------- scratch (__device__ globals; allocation-free rule) --------
__device__ float  g_d[NB * NU];          // dec proj + b1 + b2
__device__ float  g_scores[NB * NS];     // raw scores
__device__ __half g_W1Th[NU * ND];       // W1 transposed [u][k], fp16
__device__ float  g_cpart[4][NB * ND];   // context partials over s-chunks

__device__ __forceinline__ float fast_tanh(float x) {
    x = fminf(fmaxf(x, -9.0f), 9.0f);
    float e = __expf(2.0f * x);
    return __fdividef(e - 1.0f, e + 1.0f);
}
__device__ __forceinline__ uint32_t smem_u32(const void* p) {
    uint32_t a;
    asm("{ .reg .u64 t; cvta.to.shared.u64 t, %1; cvt.u32.u64 %0, t; }"
        : "=r"(a) : "l"(p));
    return a;
}
__device__ __forceinline__ void cp16(uint32_t s, const void* g) {
    asm volatile("cp.async.cg.shared.global [%0], [%1], 16;"
                 :: "r"(s), "l"(g));
}
__device__ __forceinline__ void cp_commit() {
    asm volatile("cp.async.commit_group;");
}
template <int N>
__device__ __forceinline__ void cp_wait() {
    asm volatile("cp.async.wait_group %0;" :: "n"(N));
}
__device__ __forceinline__ void mma_f16(float d[4], const uint32_t a[4],
                                        uint32_t b0, uint32_t b1) {
    asm volatile(
        "mma.sync.aligned.m16n8k16.row.col.f32.f16.f16.f32 "
        "{%0,%1,%2,%3}, {%4,%5,%6,%7}, {%8,%9}, {%0,%1,%2,%3};\n"
        : "+f"(d[0]), "+f"(d[1]), "+f"(d[2]), "+f"(d[3])
        : "r"(a[0]), "r"(a[1]), "r"(a[2]), "r"(a[3]), "r"(b0), "r"(b1));
}
__device__ __forceinline__ uint32_t pack_h2(float x, float y) {
    __half2 h = __float22half2_rn(make_float2(x, y));
    return *reinterpret_cast<uint32_t*>(&h);
}

// -------- dynamic SMEM byte layout for score kernel --------
// A tiles: 2 stages x 128 rows x 40 fp16 (stride 80B; bank-injective 20g+t)
// B tiles: 2 stages x 128 u-rows x 40 fp16 (same stride)
#define A_OFF    0u
#define STAGE_B  10240u
#define B_OFF    20480u
#define DSH_B    40960u
#define VSH_B    43008u
#define SPART_B  45056u
#define SMEM_BYTES 46080u

// ---------------- Kernel 0: W1 [k][u] fp32 -> g_W1Th [u][k] fp16 ----------------
__global__ void prep_w1(const float* __restrict__ W1) {
    __shared__ float t[32][33];
    int u0 = blockIdx.x * 32, k0 = blockIdx.y * 32;
    int x = threadIdx.x, y = threadIdx.y;
#pragma unroll
    for (int i = 0; i < 32; i += 8)
        t[y + i][x] = W1[(size_t)(k0 + y + i) * NU + u0 + x];
    __syncthreads();
#pragma unroll
    for (int i = 0; i < 32; i += 8)
        g_W1Th[(size_t)(u0 + y + i) * ND + k0 + x] = __float2half_rn(t[x][y + i]);
}

// ---------------- Kernel 1: d[b,u] = dec[b]@W2 + b1 + b2 ----------------
__global__ void dec_proj_kernel(const float* __restrict__ dec,
                                const float* __restrict__ W2,
                                const float* __restrict__ b1,
                                const float* __restrict__ b2) {
    int b = blockIdx.x, tid = threadIdx.x;
    __shared__ float ds[ND];
    ds[tid]       = dec[b * ND + tid];
    ds[tid + 256] = dec[b * ND + tid + 256];
    __syncthreads();
    int u0 = tid, u1 = tid + 256;
    float a0 = b1[u0] + b2[u0];
    float a1 = b1[u1] + b2[u1];
#pragma unroll 8
    for (int k = 0; k < ND; k++) {
        float dv = ds[k];
        a0 += dv * W2[k * NU + u0];
        a1 += dv * W2[k * NU + u1];
    }
    g_d[b * NU + u0] = a0;
    g_d[b * NU + u1] = a1;
}

// ---------------- Kernel 2: fused score, fp16 MMA, 2-stage pipeline ----------------
// 1024 CTAs x 256 thr (8 warps: 4 in M x 2 in N). Warp tile 32x64.
// A: LDG fp32 -> cvt fp16 -> STS (register double-buffered).
// B: cp.async from pre-converted g_W1Th.
__global__ __launch_bounds__(256, 2) void score_kernel(
    const float* __restrict__ enc, const float* __restrict__ V) {
    extern __shared__ __align__(16) char sm[];
    const uint32_t sbase = smem_u32(sm);

    const int tid  = threadIdx.x;
    const int warp = tid >> 5, lane = tid & 31;
    const int row0 = blockIdx.x * 128;
    const int b    = blockIdx.x >> 4;

    float* dsh   = (float*)(sm + DSH_B);
    float* vsh   = (float*)(sm + VSH_B);
    float* spart = (float*)(sm + SPART_B);
    dsh[tid]       = g_d[b * NU + tid];
    dsh[tid + 256] = g_d[b * NU + tid + 256];
    vsh[tid]       = V[tid];
    vsh[tid + 256] = V[tid + 256];
    if (tid < 256) spart[tid] = 0.0f;

    const int wm = warp & 3, wn = warp >> 2;
    const int grp = lane >> 2, t = lane & 3;
    const int mBase = wm * 32;
    const int nBase = wn * 64;

    // A copy coords: thread -> (row, 16-float half-row)
    const int ar = tid >> 1, ah = tid & 1;
    const float* aSrcRow = enc + (size_t)(row0 + ar) * ND + ah * 16;

    float4 regA[2][4];

    for (int nc = 0; nc < 4; nc++) {
        float acc[2][8][4];
#pragma unroll
        for (int i = 0; i < 2; i++)
#pragma unroll
            for (int j = 0; j < 8; j++)
#pragma unroll
                for (int e = 0; e < 4; e++) acc[i][j][e] = 0.0f;

        // Prologue: LDG A(0) -> regs; cp.async B(0) -> stage 0
#pragma unroll
        for (int j = 0; j < 4; j++)
            regA[0][j] = *reinterpret_cast<const float4*>(aSrcRow + j * 4);
#pragma unroll
        for (int j = 0; j < 2; j++) {
            int idx = tid + 256 * j;
            int br = idx >> 2, bc = idx & 3;
            cp16(sbase + B_OFF + (uint32_t)(br * 80 + bc * 16),
                 g_W1Th + (size_t)(nc * 128 + br) * ND + bc * 8);
        }
        cp_commit();

        for (int kb = 0; kb < 16; kb++) {
            const int cur = kb & 1;
            // STS A(kb): cvt fp32 regs -> fp16 smem
            {
                uint32_t* dst = (uint32_t*)(sm + A_OFF + cur * STAGE_B) +
                                ar * 20 + ah * 8;
                const float4* ra = regA[cur];
                uint4 w0 = {pack_h2(ra[0].x, ra[0].y), pack_h2(ra[0].z, ra[0].w),
                            pack_h2(ra[1].x, ra[1].y), pack_h2(ra[1].z, ra[1].w)};
                uint4 w1 = {pack_h2(ra[2].x, ra[2].y), pack_h2(ra[2].z, ra[2].w),
                            pack_h2(ra[3].x, ra[3].y), pack_h2(ra[3].z, ra[3].w)};
                *reinterpret_cast<uint4*>(dst)     = w0;
                *reinterpret_cast<uint4*>(dst + 4) = w1;
            }
            if (kb < 15) {
                const int kk = (kb + 1) * 32;
                // LDG A(kb+1) -> other reg buffer
#pragma unroll
                for (int j = 0; j < 4; j++)
                    regA[cur ^ 1][j] =
                        *reinterpret_cast<const float4*>(aSrcRow + kk + j * 4);
                // cp.async B(kb+1) -> other stage
#pragma unroll
                for (int j = 0; j < 2; j++) {
                    int idx = tid + 256 * j;
                    int br = idx >> 2, bc = idx & 3;
                    cp16(sbase + B_OFF + (uint32_t)((cur ^ 1) * STAGE_B) +
                             (uint32_t)(br * 80 + bc * 16),
                         g_W1Th + (size_t)(nc * 128 + br) * ND + kk + bc * 8);
                }
                cp_commit();
                cp_wait<1>();   // B(kb) complete
            } else {
                cp_wait<0>();
            }
            __syncthreads();

            const uint32_t* As32 = (const uint32_t*)(sm + A_OFF + cur * STAGE_B);
            const uint32_t* Bs32 = (const uint32_t*)(sm + B_OFF + cur * STAGE_B);
#pragma unroll
            for (int ks = 0; ks < 2; ks++) {
                const int kw = ks * 8 + t;
                uint32_t a[2][4];
#pragma unroll
                for (int mt = 0; mt < 2; mt++) {
                    int mr = mBase + mt * 16 + grp;
                    a[mt][0] = As32[mr * 20 + kw];
                    a[mt][1] = As32[(mr + 8) * 20 + kw];
                    a[mt][2] = As32[mr * 20 + kw + 4];
                    a[mt][3] = As32[(mr + 8) * 20 + kw + 4];
                }
#pragma unroll
                for (int nt = 0; nt < 8; nt++) {
                    int ncc = nBase + nt * 8 + grp;
                    uint32_t b0 = Bs32[ncc * 20 + kw];
                    uint32_t b1 = Bs32[ncc * 20 + kw + 4];
                    mma_f16(acc[0][nt], a[0], b0, b1);
                    mma_f16(acc[1][nt], a[1], b0, b1);
                }
            }
            __syncthreads();
        }

        // Epilogue: partial score += sum_u tanh(proj + d[b,u]) * V[u]
        float rs[2][2] = {{0.0f, 0.0f}, {0.0f, 0.0f}};
#pragma unroll
        for (int nt = 0; nt < 8; nt++) {
#pragma unroll
            for (int e = 0; e < 4; e++) {
                int u = nc * 128 + nBase + nt * 8 + 2 * t + (e & 1);
                float dv = dsh[u];
                float vv = vsh[u];
                int h = e >> 1;
                rs[0][h] += fast_tanh(acc[0][nt][e] + dv) * vv;
                rs[1][h] += fast_tanh(acc[1][nt][e] + dv) * vv;
            }
        }
#pragma unroll
        for (int mt = 0; mt < 2; mt++)
#pragma unroll
            for (int h = 0; h < 2; h++) {
                float v = rs[mt][h];
                v += __shfl_xor_sync(0xffffffffu, v, 1);
                v += __shfl_xor_sync(0xffffffffu, v, 2);
                if (t == 0) {
                    int r = mBase + mt * 16 + grp + h * 8;
                    spart[wn * 128 + r] += v;  // unique owner warp, no race
                }
            }
    }
    __syncthreads();
    if (tid < 128)
        g_scores[row0 + tid] = spart[tid] + spart[128 + tid];
}

// ---------------- Kernel 3: softmax over S per batch row ----------------
__global__ void softmax_kernel(float* __restrict__ attn_out) {
    int b = blockIdx.x, tid = threadIdx.x;
    __shared__ float red[256];
    float v[8];
    float m = -1e30f;
#pragma unroll
    for (int i = 0; i < 8; i++) {
        v[i] = g_scores[b * NS + tid + 256 * i];
        m = fmaxf(m, v[i]);
    }
    red[tid] = m;
    __syncthreads();
    for (int s = 128; s > 0; s >>= 1) {
        if (tid < s) red[tid] = fmaxf(red[tid], red[tid + s]);
        __syncthreads();
    }
    m = red[0];
    __syncthreads();
    float sum = 0.0f;
#pragma unroll
    for (int i = 0; i < 8; i++) {
        v[i] = __expf(v[i] - m);
        sum += v[i];
    }
    red[tid] = sum;
    __syncthreads();
    for (int s = 128; s > 0; s >>= 1) {
        if (tid < s) red[tid] += red[tid + s];
        __syncthreads();
    }
    float inv = 1.0f / red[0];
#pragma unroll
    for (int i = 0; i < 8; i++)
        attn_out[b * NS + tid + 256 * i] = v[i] * inv;
}

// ---------------- Kernel 4a: context partials over s-chunks ----------------
__global__ void context_part_kernel(const float* __restrict__ enc,
                                    const float* __restrict__ attn) {
    int dc = blockIdx.x, b = blockIdx.y, scch = blockIdx.z;
    int tid = threadIdx.x;
    int lx = tid & 31, ty = tid >> 5;
    __shared__ float att[512];
    __shared__ float4 redc[7][32];
    att[tid]       = attn[b * NS + scch * 512 + tid];
    att[tid + 256] = attn[b * NS + scch * 512 + tid + 256];
    __syncthreads();
    int d0 = dc * 128 + lx * 4;
    const float* basep = enc + (size_t)b * NS * ND + (size_t)scch * 512 * ND + d0;
    float4 acc = {0.0f, 0.0f, 0.0f, 0.0f};
#pragma unroll 4
    for (int s = ty; s < 512; s += 8) {
        float a = att[s];
        float4 v = *reinterpret_cast<const float4*>(basep + (size_t)s * ND);
        acc.x += a * v.x; acc.y += a * v.y;
        acc.z += a * v.z; acc.w += a * v.w;
    }
    if (ty > 0) redc[ty - 1][lx] = acc;
    __syncthreads();
    if (ty == 0) {
#pragma unroll
        for (int i = 0; i < 7; i++) {
            float4 r = redc[i][lx];
            acc.x += r.x; acc.y += r.y; acc.z += r.z; acc.w += r.w;
        }
        *reinterpret_cast<float4*>(&g_cpart[scch][b * ND + d0]) = acc;
    }
}

// ---------------- Kernel 4b: reduce partials ----------------
__global__ void context_reduce_kernel(float* __restrict__ ctx) {
    int b = blockIdx.x, tid = threadIdx.x;
#pragma unroll
    for (int d = tid; d < ND; d += 256)
        ctx[b * ND + d] = g_cpart[0][b * ND + d] + g_cpart[1][b * ND + d] +
                          g_cpart[2][b * ND + d] + g_cpart[3][b * ND + d];
}

extern "C" void kernel_launch(void* const* d_in, const int* in_sizes, int n_in,
                              void* d_out, int out_size) {
    const float* enc = (const float*)d_in[0];
    const float* dec = (const float*)d_in[1];
    const float* W1  = (const float*)d_in[2];
    const float* b1  = (const float*)d_in[3];
    const float* W2  = (const float*)d_in[4];
    const float* b2  = (const float*)d_in[5];
    const float* V   = (const float*)d_in[6];
    // d_in[7] = bv: softmax shift-invariance -> unused.

    float* ctx  = (float*)d_out;             // [64, 512]
    float* attn = (float*)d_out + NB * ND;   // [64, 2048]

    cudaFuncSetAttribute(score_kernel,
                         cudaFuncAttributeMaxDynamicSharedMemorySize,
                         SMEM_BYTES);

    prep_w1<<<dim3(16, 16), dim3(32, 8)>>>(W1);
    dec_proj_kernel<<<NB, 256>>>(dec, W2, b1, b2);
    score_kernel<<<(NB * NS) / 128, 256, SMEM_BYTES>>>(enc, V);
    softmax_kernel<<<NB, 256>>>(attn);
    context_part_kernel<<<dim3(4, NB, 4), 256>>>(enc, attn);
    context_reduce_kernel<<<NB, 256>>>(ctx);
}